// round 11
// baseline (speedup 1.0000x reference)
#include <cuda_runtime.h>

// Shapes fixed by the reference
#define BB 16
#define TT 8192
#define CC 512
#define YY 256
#define C4 (CC / 4)            // 128 float4 lanes per frame row
#define NSPAN (BB * YY)        // 4096
#define GRID_POOL (148 * 8)    // 8 blocks/SM: RF-limited optimum (64 regs)

// Work-stealing state (module-static, self-restoring each launch)
__device__ int g_next = GRID_POOL;
__device__ int g_done = 0;

// ---------------------------------------------------------------------------
// Single fused persistent kernel.
// Startup (once per block): scan ALL durations (16 KB) into a shared cumsum
// table. 4 warps x 4 batches each; per batch: 8 elems/lane serial prefix +
// warp scan -> 256-entry inclusive cumsum. After this, per-span metadata is
// two broadcast LDS reads — no per-span global loads, no reductions.
// Main loop: steal whole spans in span order (best measured DRAM page
// locality); 128 threads = one float4 lane each -> contiguous 2048B per
// frame row; unroll-4, 4 independent accumulators, plain loads (the
// R3-proven 76%-DRAM loop, byte-identical).
// Last block restores steal counters (graph-replay safe, deterministic).
// ---------------------------------------------------------------------------
__global__ void __launch_bounds__(128, 8)
pool_fused_kernel(const float* __restrict__ emg,
                  const int*   __restrict__ dur,
                  float*       __restrict__ out) {
    __shared__ int sh_cum[NSPAN];    // 16 KB inclusive cumsum (per batch)
    __shared__ int sh_next;
    const int tid  = threadIdx.x;    // 0..127
    const int wid  = tid >> 5;
    const int lane = tid & 31;

    // ---- one-time full cumsum of durations into shared ----
    const int4* dur4 = reinterpret_cast<const int4*>(dur);
    for (int b = wid; b < BB; b += 4) {
        const int4 u = __ldg(dur4 + b * 64 + lane * 2);
        const int4 v = __ldg(dur4 + b * 64 + lane * 2 + 1);
        const int e0 = u.x;
        const int e1 = e0 + u.y;
        const int e2 = e1 + u.z;
        const int e3 = e2 + u.w;
        const int e4 = e3 + v.x;
        const int e5 = e4 + v.y;
        const int e6 = e5 + v.z;
        const int e7 = e6 + v.w;
        int sc = e7;                           // inclusive warp scan of totals
        #pragma unroll
        for (int o = 1; o < 32; o <<= 1) {
            const int t = __shfl_up_sync(0xffffffffu, sc, o);
            if (lane >= o) sc += t;
        }
        const int excl = sc - e7;
        const int base = b * YY + lane * 8;
        sh_cum[base + 0] = excl + e0;
        sh_cum[base + 1] = excl + e1;
        sh_cum[base + 2] = excl + e2;
        sh_cum[base + 3] = excl + e3;
        sh_cum[base + 4] = excl + e4;
        sh_cum[base + 5] = excl + e5;
        sh_cum[base + 6] = excl + e6;
        sh_cum[base + 7] = excl + e7;
    }
    __syncthreads();

    // ---- persistent span loop ----
    int by = blockIdx.x;
    while (by < NSPAN) {
        // prefetch next span id (atomic latency hidden under the frame loop)
        if (tid == 0) sh_next = atomicAdd(&g_next, 1);

        const int b = by >> 8;       // YY == 256
        const int y = by & 255;

        // span metadata: two broadcast LDS reads
        const int en_raw = sh_cum[by];
        const int st_raw = y ? sh_cum[by - 1] : 0;
        const int st  = min(st_raw, TT);
        const int en  = min(en_raw, TT);
        const int cnt = en - st;

        // ---- mean-pool cnt frames (R3 loop, byte-identical) ----
        const float4* p = reinterpret_cast<const float4*>(emg)
                          + ((size_t)b * TT + st) * C4 + tid;

        float4 a0 = make_float4(0.f, 0.f, 0.f, 0.f);
        float4 a1 = a0, a2 = a0, a3 = a0;

        int t = 0;
        for (; t + 4 <= cnt; t += 4) {
            const float4 v0 = p[0 * C4];
            const float4 v1 = p[1 * C4];
            const float4 v2 = p[2 * C4];
            const float4 v3 = p[3 * C4];
            a0.x += v0.x; a0.y += v0.y; a0.z += v0.z; a0.w += v0.w;
            a1.x += v1.x; a1.y += v1.y; a1.z += v1.z; a1.w += v1.w;
            a2.x += v2.x; a2.y += v2.y; a2.z += v2.z; a2.w += v2.w;
            a3.x += v3.x; a3.y += v3.y; a3.z += v3.z; a3.w += v3.w;
            p += 4 * C4;
        }
        for (; t < cnt; t++) {
            const float4 vv = p[0];
            a0.x += vv.x; a0.y += vv.y; a0.z += vv.z; a0.w += vv.w;
            p += C4;
        }

        const float inv = (cnt > 0) ? (1.0f / (float)cnt) : 0.0f;
        float4 r;
        r.x = ((a0.x + a1.x) + (a2.x + a3.x)) * inv;
        r.y = ((a0.y + a1.y) + (a2.y + a3.y)) * inv;
        r.z = ((a0.z + a1.z) + (a2.z + a3.z)) * inv;
        r.w = ((a0.w + a1.w) + (a2.w + a3.w)) * inv;

        reinterpret_cast<float4*>(out)[(size_t)by * C4 + tid] = r;

        // consume prefetched span id
        __syncthreads();
        by = sh_next;
        __syncthreads();
    }

    // ---- last block restores steal state for the next (graph) launch ----
    if (tid == 0) {
        const int d = atomicAdd(&g_done, 1);
        if (d == GRID_POOL - 1) {
            g_next = GRID_POOL;
            g_done = 0;
            __threadfence();
        }
    }
}

extern "C" void kernel_launch(void* const* d_in, const int* in_sizes, int n_in,
                              void* d_out, int out_size) {
    const float* emg = (const float*)d_in[0];
    const int*   dur = (const int*)d_in[1];
    float*       out = (float*)d_out;

    pool_fused_kernel<<<GRID_POOL, 128>>>(emg, dur, out);
}

// round 12
// speedup vs baseline: 1.1217x; 1.1217x over previous
#include <cuda_runtime.h>
#include <cstdint>

// Shapes fixed by the reference
#define BB 16
#define TT 8192
#define CC 512
#define C4 (CC / 4)              // 128 float4 lanes per frame row
#define YY 256
#define NSPAN (BB * YY)          // 4096
#define ROWB (CC * 4)            // 2048 bytes per frame row
#define RPC 4                    // rows per chunk
#define CHUNKB (RPC * ROWB)      // 8192 bytes per stage
#define STAGES 4
#define NCONS 128                // consumer threads (4 warps)
#define NTHR (NCONS + 32)        // + 1 producer warp
#define BLKS 6                   // blocks/SM: 6 x 33KB smem <= 228KB
#define GRID_POOL (148 * BLKS)   // 888

// Steal state (self-restoring each launch; graph-replay safe)
__device__ int g_next = GRID_POOL;
__device__ int g_done = 0;

// ---------------- mbarrier / bulk-copy primitives ----------------
__device__ __forceinline__ uint32_t sm32(const void* p) {
    return (uint32_t)__cvta_generic_to_shared(p);
}
__device__ __forceinline__ void mbar_init(uint32_t a, uint32_t cnt) {
    asm volatile("mbarrier.init.shared.b64 [%0], %1;" :: "r"(a), "r"(cnt) : "memory");
}
__device__ __forceinline__ void mbar_expect_tx(uint32_t a, uint32_t bytes) {
    asm volatile("mbarrier.arrive.expect_tx.shared.b64 _, [%0], %1;"
                 :: "r"(a), "r"(bytes) : "memory");
}
__device__ __forceinline__ void mbar_arrive(uint32_t a) {
    asm volatile("mbarrier.arrive.shared.b64 _, [%0];" :: "r"(a) : "memory");
}
__device__ __forceinline__ void mbar_wait(uint32_t a, uint32_t parity) {
    uint32_t done;
    asm volatile("{\n\t.reg .pred p;\n\t"
                 "mbarrier.try_wait.parity.acquire.cta.shared::cta.b64 p, [%1], %2;\n\t"
                 "selp.b32 %0, 1, 0, p;\n\t}"
                 : "=r"(done) : "r"(a), "r"(parity) : "memory");
    while (!done) {
        asm volatile("{\n\t.reg .pred p;\n\t"
                     "mbarrier.try_wait.parity.acquire.cta.shared::cta.b64 p, [%1], %2, 0x989680;\n\t"
                     "selp.b32 %0, 1, 0, p;\n\t}"
                     : "=r"(done) : "r"(a), "r"(parity) : "memory");
    }
}
__device__ __forceinline__ void bulk_g2s(uint32_t dst, const void* src,
                                         uint32_t bytes, uint32_t mbar) {
    asm volatile("cp.async.bulk.shared::cta.global.mbarrier::complete_tx::bytes "
                 "[%0], [%1], %2, [%3];"
                 :: "r"(dst), "l"(src), "r"(bytes), "r"(mbar) : "memory");
}

// ---------------------------------------------------------------------------
// Warp-specialized persistent kernel.
// Producer warp (tid 128..159): steals spans, computes metadata via 32-lane
// reduce over the (L1-resident) durations row, writes zero-spans directly,
// and streams span data into a 4-stage smem ring via cp.async.bulk
// (8KB/chunk, register-free in-flight bytes). Terminal descriptor (by=-1)
// shuts consumers down.
// Consumer warps (tid 0..127): one float4 channel lane each; per chunk read
// <=4 rows from smem, accumulate; on the span's last chunk scale by 1/cnt
// and store. Sequential accumulation -> bitwise deterministic.
// ---------------------------------------------------------------------------
__global__ void __launch_bounds__(NTHR, BLKS)
pool_tma_kernel(const float* __restrict__ emg,
                const int*   __restrict__ dur,
                float*       __restrict__ out) {
    __shared__ alignas(128) float4 buf[STAGES][RPC * C4];   // 32 KB ring
    __shared__ alignas(16)  int4   desc[STAGES];            // {by, rows, inv, last}
    __shared__ alignas(8)   unsigned long long mb_full[STAGES];
    __shared__ alignas(8)   unsigned long long mb_empty[STAGES];

    const int tid = threadIdx.x;

    if (tid == 0) {
        #pragma unroll
        for (int s = 0; s < STAGES; s++) {
            mbar_init(sm32(&mb_full[s]),  1);   // producer arrive (expect_tx) + tx
            mbar_init(sm32(&mb_empty[s]), 4);   // one arrive per consumer warp
        }
    }
    __syncthreads();

    if (tid >= NCONS) {
        // ===================== PRODUCER WARP =====================
        const int lane = tid - NCONS;          // 0..31
        const bool leader = (lane == 0);
        const int4* dur4 = reinterpret_cast<const int4*>(dur);
        long pidx = 0;                          // global chunk index

        int by = blockIdx.x;
        while (by < NSPAN) {
            int nxt = 0;
            if (leader) nxt = atomicAdd(&g_next, 1);   // steal early

            const int b = by >> 8;             // YY == 256
            const int y = by & 255;

            // metadata: 32 lanes x 8 durations each
            const int4 u = __ldg(dur4 + b * 64 + lane * 2);
            const int4 v = __ldg(dur4 + b * 64 + lane * 2 + 1);
            const int base = lane * 8;
            int s = 0;
            if (base + 0 < y) s += u.x;
            if (base + 1 < y) s += u.y;
            if (base + 2 < y) s += u.z;
            if (base + 3 < y) s += u.w;
            if (base + 4 < y) s += v.x;
            if (base + 5 < y) s += v.y;
            if (base + 6 < y) s += v.z;
            if (base + 7 < y) s += v.w;
            int c_lane = 0;
            if ((y >> 3) == lane) {
                switch (y & 7) {
                    case 0:  c_lane = u.x; break;
                    case 1:  c_lane = u.y; break;
                    case 2:  c_lane = u.z; break;
                    case 3:  c_lane = u.w; break;
                    case 4:  c_lane = v.x; break;
                    case 5:  c_lane = v.y; break;
                    case 6:  c_lane = v.z; break;
                    default: c_lane = v.w; break;
                }
            }
            const int start_raw = __reduce_add_sync(0xffffffffu, s);
            const int dcnt = __shfl_sync(0xffffffffu, c_lane, y >> 3);
            const int st  = min(start_raw, TT);
            const int en  = min(start_raw + dcnt, TT);
            const int cnt = en - st;

            if (cnt == 0) {
                // empty span: producer writes the zeros itself
                const float4 z = make_float4(0.f, 0.f, 0.f, 0.f);
                float4* o = reinterpret_cast<float4*>(out) + (size_t)by * C4;
                o[lane]      = z;
                o[lane + 32] = z;
                o[lane + 64] = z;
                o[lane + 96] = z;
            } else {
                const char* src = reinterpret_cast<const char*>(emg)
                                  + ((size_t)b * TT + st) * ROWB;
                const float inv = 1.0f / (float)cnt;
                const int nch = (cnt + RPC - 1) >> 2;
                for (int c = 0; c < nch; c++) {
                    if (leader) {
                        const int rows = min(cnt - c * RPC, RPC);
                        const int stg  = (int)(pidx & (STAGES - 1));
                        const uint32_t ph = 1u ^ (uint32_t)((pidx >> 2) & 1);
                        mbar_wait(sm32(&mb_empty[stg]), ph);
                        desc[stg] = make_int4(by, rows, __float_as_int(inv),
                                              (c == nch - 1) ? 1 : 0);
                        mbar_expect_tx(sm32(&mb_full[stg]), rows * ROWB);
                        bulk_g2s(sm32(&buf[stg][0]), src + (size_t)c * CHUNKB,
                                 rows * ROWB, sm32(&mb_full[stg]));
                    }
                    pidx++;
                }
            }
            by = __shfl_sync(0xffffffffu, nxt, 0);
        }

        // terminal descriptor (dummy 16B copy satisfies the tx count)
        if (leader) {
            const int stg = (int)(pidx & (STAGES - 1));
            const uint32_t ph = 1u ^ (uint32_t)((pidx >> 2) & 1);
            mbar_wait(sm32(&mb_empty[stg]), ph);
            desc[stg] = make_int4(-1, 0, 0, 0);
            mbar_expect_tx(sm32(&mb_full[stg]), 16);
            bulk_g2s(sm32(&buf[stg][0]), emg, 16, sm32(&mb_full[stg]));
        }
    } else {
        // ===================== CONSUMER WARPS =====================
        long cidx = 0;
        float4 acc = make_float4(0.f, 0.f, 0.f, 0.f);
        for (;;) {
            const int stg = (int)(cidx & (STAGES - 1));
            const uint32_t ph = (uint32_t)((cidx >> 2) & 1);
            mbar_wait(sm32(&mb_full[stg]), ph);
            const int4 d = desc[stg];          // broadcast LDS
            if (d.x < 0) break;                // terminal

            const float4* sp = &buf[stg][tid];
            if (d.y == RPC) {                  // common case: 4 rows
                const float4 v0 = sp[0 * C4];
                const float4 v1 = sp[1 * C4];
                const float4 v2 = sp[2 * C4];
                const float4 v3 = sp[3 * C4];
                acc.x += (v0.x + v1.x) + (v2.x + v3.x);
                acc.y += (v0.y + v1.y) + (v2.y + v3.y);
                acc.z += (v0.z + v1.z) + (v2.z + v3.z);
                acc.w += (v0.w + v1.w) + (v2.w + v3.w);
            } else {
                for (int r = 0; r < d.y; r++) {
                    const float4 vv = sp[r * C4];
                    acc.x += vv.x; acc.y += vv.y; acc.z += vv.z; acc.w += vv.w;
                }
            }

            if (d.w) {                         // last chunk of span
                const float inv = __int_as_float(d.z);
                float4 r;
                r.x = acc.x * inv; r.y = acc.y * inv;
                r.z = acc.z * inv; r.w = acc.w * inv;
                reinterpret_cast<float4*>(out)[(size_t)d.x * C4 + tid] = r;
                acc = make_float4(0.f, 0.f, 0.f, 0.f);
            }

            __syncwarp();
            if ((tid & 31) == 0) mbar_arrive(sm32(&mb_empty[stg]));
            cidx++;
        }
    }

    // last block restores steal state for the next (graph) replay
    __syncthreads();
    if (tid == 0) {
        const int dd = atomicAdd(&g_done, 1);
        if (dd == GRID_POOL - 1) {
            g_next = GRID_POOL;
            g_done = 0;
            __threadfence();
        }
    }
}

extern "C" void kernel_launch(void* const* d_in, const int* in_sizes, int n_in,
                              void* d_out, int out_size) {
    const float* emg = (const float*)d_in[0];
    const int*   dur = (const int*)d_in[1];
    float*       out = (float*)d_out;

    pool_tma_kernel<<<GRID_POOL, NTHR>>>(emg, dur, out);
}

// round 13
// speedup vs baseline: 1.1453x; 1.0210x over previous
#include <cuda_runtime.h>
#include <cstdint>

// Shapes fixed by the reference
#define BB 16
#define TT 8192
#define CC 512
#define C4 (CC / 4)              // 128 float4 lanes per frame row
#define YY 256
#define NSPAN (BB * YY)          // 4096
#define ROWB (CC * 4)            // 2048 bytes per frame row
#define RPC 8                    // rows per chunk
#define CHUNKB (RPC * ROWB)      // 16384 bytes per stage
#define STAGES 4
#define NCONS 128                // consumer threads (4 warps)
#define NTHR (NCONS + 32)        // + 1 producer warp
#define BLKS 3                   // blocks/SM: 3 x 64KB ring <= 228KB smem
#define GRID_POOL (148 * BLKS)   // 444

// Steal state (self-restoring each launch; graph-replay safe)
__device__ int g_next = GRID_POOL;
__device__ int g_done = 0;

// ---------------- mbarrier / bulk-copy primitives ----------------
__device__ __forceinline__ uint32_t sm32(const void* p) {
    return (uint32_t)__cvta_generic_to_shared(p);
}
__device__ __forceinline__ void mbar_init(uint32_t a, uint32_t cnt) {
    asm volatile("mbarrier.init.shared.b64 [%0], %1;" :: "r"(a), "r"(cnt) : "memory");
}
__device__ __forceinline__ void mbar_expect_tx(uint32_t a, uint32_t bytes) {
    asm volatile("mbarrier.arrive.expect_tx.shared.b64 _, [%0], %1;"
                 :: "r"(a), "r"(bytes) : "memory");
}
__device__ __forceinline__ void mbar_arrive(uint32_t a) {
    asm volatile("mbarrier.arrive.shared.b64 _, [%0];" :: "r"(a) : "memory");
}
__device__ __forceinline__ void mbar_wait(uint32_t a, uint32_t parity) {
    uint32_t done;
    asm volatile("{\n\t.reg .pred p;\n\t"
                 "mbarrier.try_wait.parity.acquire.cta.shared::cta.b64 p, [%1], %2;\n\t"
                 "selp.b32 %0, 1, 0, p;\n\t}"
                 : "=r"(done) : "r"(a), "r"(parity) : "memory");
    while (!done) {
        asm volatile("{\n\t.reg .pred p;\n\t"
                     "mbarrier.try_wait.parity.acquire.cta.shared::cta.b64 p, [%1], %2, 0x989680;\n\t"
                     "selp.b32 %0, 1, 0, p;\n\t}"
                     : "=r"(done) : "r"(a), "r"(parity) : "memory");
    }
}
__device__ __forceinline__ void bulk_g2s(uint32_t dst, const void* src,
                                         uint32_t bytes, uint32_t mbar) {
    asm volatile("cp.async.bulk.shared::cta.global.mbarrier::complete_tx::bytes "
                 "[%0], [%1], %2, [%3];"
                 :: "r"(dst), "l"(src), "r"(bytes), "r"(mbar) : "memory");
}

// ---------------------------------------------------------------------------
// Warp-specialized persistent kernel (R12 architecture, 16KB chunks).
// Producer warp: steals spans, computes metadata (32-lane reduce over the
// L1-resident durations row), writes zero-spans, streams span data into a
// 4-stage x 16KB smem ring via cp.async.bulk. Terminal descriptor (by=-1).
// Consumer warps (128 threads = one float4 lane each): accumulate rows from
// smem per chunk; on a span's last chunk scale by 1/cnt and store.
// Sequential per-span accumulation -> bitwise deterministic.
// ---------------------------------------------------------------------------
__global__ void __launch_bounds__(NTHR, BLKS)
pool_tma_kernel(const float* __restrict__ emg,
                const int*   __restrict__ dur,
                float*       __restrict__ out) {
    __shared__ alignas(128) float4 buf[STAGES][RPC * C4];   // 64 KB ring
    __shared__ alignas(16)  int4   desc[STAGES];            // {by, rows, inv, last}
    __shared__ alignas(8)   unsigned long long mb_full[STAGES];
    __shared__ alignas(8)   unsigned long long mb_empty[STAGES];

    const int tid = threadIdx.x;

    if (tid == 0) {
        #pragma unroll
        for (int s = 0; s < STAGES; s++) {
            mbar_init(sm32(&mb_full[s]),  1);   // producer arrive (expect_tx) + tx
            mbar_init(sm32(&mb_empty[s]), 4);   // one arrive per consumer warp
        }
    }
    __syncthreads();

    if (tid >= NCONS) {
        // ===================== PRODUCER WARP =====================
        const int lane = tid - NCONS;          // 0..31
        const bool leader = (lane == 0);
        const int4* dur4 = reinterpret_cast<const int4*>(dur);
        long pidx = 0;                          // global chunk index

        int by = blockIdx.x;
        while (by < NSPAN) {
            int nxt = 0;
            if (leader) nxt = atomicAdd(&g_next, 1);   // steal early

            const int b = by >> 8;             // YY == 256
            const int y = by & 255;

            // metadata: 32 lanes x 8 durations each
            const int4 u = __ldg(dur4 + b * 64 + lane * 2);
            const int4 v = __ldg(dur4 + b * 64 + lane * 2 + 1);
            const int base = lane * 8;
            int s = 0;
            if (base + 0 < y) s += u.x;
            if (base + 1 < y) s += u.y;
            if (base + 2 < y) s += u.z;
            if (base + 3 < y) s += u.w;
            if (base + 4 < y) s += v.x;
            if (base + 5 < y) s += v.y;
            if (base + 6 < y) s += v.z;
            if (base + 7 < y) s += v.w;
            int c_lane = 0;
            if ((y >> 3) == lane) {
                switch (y & 7) {
                    case 0:  c_lane = u.x; break;
                    case 1:  c_lane = u.y; break;
                    case 2:  c_lane = u.z; break;
                    case 3:  c_lane = u.w; break;
                    case 4:  c_lane = v.x; break;
                    case 5:  c_lane = v.y; break;
                    case 6:  c_lane = v.z; break;
                    default: c_lane = v.w; break;
                }
            }
            const int start_raw = __reduce_add_sync(0xffffffffu, s);
            const int dcnt = __shfl_sync(0xffffffffu, c_lane, y >> 3);
            const int st  = min(start_raw, TT);
            const int en  = min(start_raw + dcnt, TT);
            const int cnt = en - st;

            if (cnt == 0) {
                // empty span: producer writes the zeros itself
                const float4 z = make_float4(0.f, 0.f, 0.f, 0.f);
                float4* o = reinterpret_cast<float4*>(out) + (size_t)by * C4;
                o[lane]      = z;
                o[lane + 32] = z;
                o[lane + 64] = z;
                o[lane + 96] = z;
            } else {
                const char* src = reinterpret_cast<const char*>(emg)
                                  + ((size_t)b * TT + st) * ROWB;
                const float inv = 1.0f / (float)cnt;
                const int nch = (cnt + RPC - 1) >> 3;
                for (int c = 0; c < nch; c++) {
                    if (leader) {
                        const int rows = min(cnt - c * RPC, RPC);
                        const int stg  = (int)(pidx & (STAGES - 1));
                        const uint32_t ph = 1u ^ (uint32_t)((pidx >> 2) & 1);
                        mbar_wait(sm32(&mb_empty[stg]), ph);
                        desc[stg] = make_int4(by, rows, __float_as_int(inv),
                                              (c == nch - 1) ? 1 : 0);
                        mbar_expect_tx(sm32(&mb_full[stg]), rows * ROWB);
                        bulk_g2s(sm32(&buf[stg][0]), src + (size_t)c * CHUNKB,
                                 rows * ROWB, sm32(&mb_full[stg]));
                    }
                    pidx++;
                }
            }
            by = __shfl_sync(0xffffffffu, nxt, 0);
        }

        // terminal descriptor (dummy 16B copy satisfies the tx count)
        if (leader) {
            const int stg = (int)(pidx & (STAGES - 1));
            const uint32_t ph = 1u ^ (uint32_t)((pidx >> 2) & 1);
            mbar_wait(sm32(&mb_empty[stg]), ph);
            desc[stg] = make_int4(-1, 0, 0, 0);
            mbar_expect_tx(sm32(&mb_full[stg]), 16);
            bulk_g2s(sm32(&buf[stg][0]), emg, 16, sm32(&mb_full[stg]));
        }
    } else {
        // ===================== CONSUMER WARPS =====================
        long cidx = 0;
        float4 acc = make_float4(0.f, 0.f, 0.f, 0.f);
        for (;;) {
            const int stg = (int)(cidx & (STAGES - 1));
            const uint32_t ph = (uint32_t)((cidx >> 2) & 1);
            mbar_wait(sm32(&mb_full[stg]), ph);
            const int4 d = desc[stg];          // broadcast LDS
            if (d.x < 0) break;                // terminal

            const float4* sp = &buf[stg][tid];
            if (d.y == RPC) {                  // common case: 8 rows
                const float4 v0 = sp[0 * C4];
                const float4 v1 = sp[1 * C4];
                const float4 v2 = sp[2 * C4];
                const float4 v3 = sp[3 * C4];
                const float4 v4 = sp[4 * C4];
                const float4 v5 = sp[5 * C4];
                const float4 v6 = sp[6 * C4];
                const float4 v7 = sp[7 * C4];
                acc.x += ((v0.x + v1.x) + (v2.x + v3.x)) + ((v4.x + v5.x) + (v6.x + v7.x));
                acc.y += ((v0.y + v1.y) + (v2.y + v3.y)) + ((v4.y + v5.y) + (v6.y + v7.y));
                acc.z += ((v0.z + v1.z) + (v2.z + v3.z)) + ((v4.z + v5.z) + (v6.z + v7.z));
                acc.w += ((v0.w + v1.w) + (v2.w + v3.w)) + ((v4.w + v5.w) + (v6.w + v7.w));
            } else {
                for (int r = 0; r < d.y; r++) {
                    const float4 vv = sp[r * C4];
                    acc.x += vv.x; acc.y += vv.y; acc.z += vv.z; acc.w += vv.w;
                }
            }

            if (d.w) {                         // last chunk of span
                const float inv = __int_as_float(d.z);
                float4 r;
                r.x = acc.x * inv; r.y = acc.y * inv;
                r.z = acc.z * inv; r.w = acc.w * inv;
                reinterpret_cast<float4*>(out)[(size_t)d.x * C4 + tid] = r;
                acc = make_float4(0.f, 0.f, 0.f, 0.f);
            }

            __syncwarp();
            if ((tid & 31) == 0) mbar_arrive(sm32(&mb_empty[stg]));
            cidx++;
        }
    }

    // last block restores steal state for the next (graph) replay
    __syncthreads();
    if (tid == 0) {
        const int dd = atomicAdd(&g_done, 1);
        if (dd == GRID_POOL - 1) {
            g_next = GRID_POOL;
            g_done = 0;
            __threadfence();
        }
    }
}

extern "C" void kernel_launch(void* const* d_in, const int* in_sizes, int n_in,
                              void* d_out, int out_size) {
    const float* emg = (const float*)d_in[0];
    const int*   dur = (const int*)d_in[1];
    float*       out = (float*)d_out;

    pool_tma_kernel<<<GRID_POOL, NTHR>>>(emg, dur, out);
}

// round 14
// speedup vs baseline: 1.1634x; 1.0159x over previous
#include <cuda_runtime.h>
#include <cstdint>

// Shapes fixed by the reference
#define BB 16
#define TT 8192
#define CC 512
#define C4 (CC / 4)              // 128 float4 lanes per frame row
#define YY 256
#define NSPAN (BB * YY)          // 4096
#define ROWB (CC * 4)            // 2048 bytes per frame row
#define RPC 16                   // rows per chunk
#define CHUNKB (RPC * ROWB)      // 32768 bytes per stage
#define STAGES 3
#define NCONS 128                // consumer threads (4 warps)
#define NTHR (NCONS + 32)        // + 1 producer warp
#define BLKS 2                   // blocks/SM: 2 x 96KB ring <= 228KB smem
#define GRID_POOL (148 * BLKS)   // 296

// Steal state (self-restoring each launch; graph-replay safe)
__device__ int g_next = GRID_POOL;
__device__ int g_done = 0;

// ---------------- mbarrier / bulk-copy primitives ----------------
__device__ __forceinline__ uint32_t sm32(const void* p) {
    return (uint32_t)__cvta_generic_to_shared(p);
}
__device__ __forceinline__ void mbar_init(uint32_t a, uint32_t cnt) {
    asm volatile("mbarrier.init.shared.b64 [%0], %1;" :: "r"(a), "r"(cnt) : "memory");
}
__device__ __forceinline__ void mbar_expect_tx(uint32_t a, uint32_t bytes) {
    asm volatile("mbarrier.arrive.expect_tx.shared.b64 _, [%0], %1;"
                 :: "r"(a), "r"(bytes) : "memory");
}
__device__ __forceinline__ void mbar_arrive(uint32_t a) {
    asm volatile("mbarrier.arrive.shared.b64 _, [%0];" :: "r"(a) : "memory");
}
__device__ __forceinline__ void mbar_wait(uint32_t a, uint32_t parity) {
    uint32_t done;
    asm volatile("{\n\t.reg .pred p;\n\t"
                 "mbarrier.try_wait.parity.acquire.cta.shared::cta.b64 p, [%1], %2;\n\t"
                 "selp.b32 %0, 1, 0, p;\n\t}"
                 : "=r"(done) : "r"(a), "r"(parity) : "memory");
    while (!done) {
        asm volatile("{\n\t.reg .pred p;\n\t"
                     "mbarrier.try_wait.parity.acquire.cta.shared::cta.b64 p, [%1], %2, 0x989680;\n\t"
                     "selp.b32 %0, 1, 0, p;\n\t}"
                     : "=r"(done) : "r"(a), "r"(parity) : "memory");
    }
}
__device__ __forceinline__ void bulk_g2s(uint32_t dst, const void* src,
                                         uint32_t bytes, uint32_t mbar) {
    asm volatile("cp.async.bulk.shared::cta.global.mbarrier::complete_tx::bytes "
                 "[%0], [%1], %2, [%3];"
                 :: "r"(dst), "l"(src), "r"(bytes), "r"(mbar) : "memory");
}

// ---------------------------------------------------------------------------
// Warp-specialized persistent kernel (R13 architecture, 32KB chunks,
// 3-stage ring with explicit stage/phase cursors).
// Producer warp: steals spans, computes metadata (32-lane reduce over the
// L1-resident durations row), writes zero-spans, streams span data into the
// ring via cp.async.bulk. Terminal descriptor (by=-1) shuts consumers down.
// Consumer warps (128 threads = one float4 lane each): accumulate rows from
// smem per chunk; on a span's last chunk scale by 1/cnt and store.
// Sequential per-span accumulation -> bitwise deterministic.
// ---------------------------------------------------------------------------
__global__ void __launch_bounds__(NTHR, BLKS)
pool_tma_kernel(const float* __restrict__ emg,
                const int*   __restrict__ dur,
                float*       __restrict__ out) {
    __shared__ alignas(128) float4 buf[STAGES][RPC * C4];   // 96 KB ring
    __shared__ alignas(16)  int4   desc[STAGES];            // {by, rows, inv, last}
    __shared__ alignas(8)   unsigned long long mb_full[STAGES];
    __shared__ alignas(8)   unsigned long long mb_empty[STAGES];

    const int tid = threadIdx.x;

    if (tid == 0) {
        #pragma unroll
        for (int s = 0; s < STAGES; s++) {
            mbar_init(sm32(&mb_full[s]),  1);   // producer arrive (expect_tx) + tx
            mbar_init(sm32(&mb_empty[s]), 4);   // one arrive per consumer warp
        }
    }
    __syncthreads();

    if (tid >= NCONS) {
        // ===================== PRODUCER WARP =====================
        const int lane = tid - NCONS;          // 0..31
        const bool leader = (lane == 0);
        const int4* dur4 = reinterpret_cast<const int4*>(dur);
        int p_stg = 0, p_ph = 1;               // producer cursor (phase starts 1)

        int by = blockIdx.x;
        while (by < NSPAN) {
            int nxt = 0;
            if (leader) nxt = atomicAdd(&g_next, 1);   // steal early

            const int b = by >> 8;             // YY == 256
            const int y = by & 255;

            // metadata: 32 lanes x 8 durations each
            const int4 u = __ldg(dur4 + b * 64 + lane * 2);
            const int4 v = __ldg(dur4 + b * 64 + lane * 2 + 1);
            const int base = lane * 8;
            int s = 0;
            if (base + 0 < y) s += u.x;
            if (base + 1 < y) s += u.y;
            if (base + 2 < y) s += u.z;
            if (base + 3 < y) s += u.w;
            if (base + 4 < y) s += v.x;
            if (base + 5 < y) s += v.y;
            if (base + 6 < y) s += v.z;
            if (base + 7 < y) s += v.w;
            int c_lane = 0;
            if ((y >> 3) == lane) {
                switch (y & 7) {
                    case 0:  c_lane = u.x; break;
                    case 1:  c_lane = u.y; break;
                    case 2:  c_lane = u.z; break;
                    case 3:  c_lane = u.w; break;
                    case 4:  c_lane = v.x; break;
                    case 5:  c_lane = v.y; break;
                    case 6:  c_lane = v.z; break;
                    default: c_lane = v.w; break;
                }
            }
            const int start_raw = __reduce_add_sync(0xffffffffu, s);
            const int dcnt = __shfl_sync(0xffffffffu, c_lane, y >> 3);
            const int st  = min(start_raw, TT);
            const int en  = min(start_raw + dcnt, TT);
            const int cnt = en - st;

            if (cnt == 0) {
                // empty span: producer writes the zeros itself
                const float4 z = make_float4(0.f, 0.f, 0.f, 0.f);
                float4* o = reinterpret_cast<float4*>(out) + (size_t)by * C4;
                o[lane]      = z;
                o[lane + 32] = z;
                o[lane + 64] = z;
                o[lane + 96] = z;
            } else if (leader) {
                const char* src = reinterpret_cast<const char*>(emg)
                                  + ((size_t)b * TT + st) * ROWB;
                const float inv = 1.0f / (float)cnt;
                const int nch = (cnt + RPC - 1) >> 4;
                for (int c = 0; c < nch; c++) {
                    const int rows = min(cnt - c * RPC, RPC);
                    mbar_wait(sm32(&mb_empty[p_stg]), p_ph);
                    desc[p_stg] = make_int4(by, rows, __float_as_int(inv),
                                            (c == nch - 1) ? 1 : 0);
                    mbar_expect_tx(sm32(&mb_full[p_stg]), rows * ROWB);
                    bulk_g2s(sm32(&buf[p_stg][0]), src + (size_t)c * CHUNKB,
                             rows * ROWB, sm32(&mb_full[p_stg]));
                    if (++p_stg == STAGES) { p_stg = 0; p_ph ^= 1; }
                }
            }
            by = __shfl_sync(0xffffffffu, nxt, 0);
        }

        // terminal descriptor (dummy 16B copy satisfies the tx count)
        if (leader) {
            mbar_wait(sm32(&mb_empty[p_stg]), p_ph);
            desc[p_stg] = make_int4(-1, 0, 0, 0);
            mbar_expect_tx(sm32(&mb_full[p_stg]), 16);
            bulk_g2s(sm32(&buf[p_stg][0]), emg, 16, sm32(&mb_full[p_stg]));
        }
    } else {
        // ===================== CONSUMER WARPS =====================
        int c_stg = 0, c_ph = 0;               // consumer cursor (phase starts 0)
        float4 acc = make_float4(0.f, 0.f, 0.f, 0.f);
        for (;;) {
            mbar_wait(sm32(&mb_full[c_stg]), c_ph);
            const int4 d = desc[c_stg];        // broadcast LDS
            if (d.x < 0) break;                // terminal

            const float4* sp = &buf[c_stg][tid];
            if (d.y == RPC) {                  // common case: 16 rows
                float4 s0 = make_float4(0.f, 0.f, 0.f, 0.f);
                float4 s1 = s0, s2 = s0, s3 = s0;
                #pragma unroll
                for (int r = 0; r < RPC; r += 4) {
                    const float4 v0 = sp[(r + 0) * C4];
                    const float4 v1 = sp[(r + 1) * C4];
                    const float4 v2 = sp[(r + 2) * C4];
                    const float4 v3 = sp[(r + 3) * C4];
                    s0.x += v0.x; s0.y += v0.y; s0.z += v0.z; s0.w += v0.w;
                    s1.x += v1.x; s1.y += v1.y; s1.z += v1.z; s1.w += v1.w;
                    s2.x += v2.x; s2.y += v2.y; s2.z += v2.z; s2.w += v2.w;
                    s3.x += v3.x; s3.y += v3.y; s3.z += v3.z; s3.w += v3.w;
                }
                acc.x += (s0.x + s1.x) + (s2.x + s3.x);
                acc.y += (s0.y + s1.y) + (s2.y + s3.y);
                acc.z += (s0.z + s1.z) + (s2.z + s3.z);
                acc.w += (s0.w + s1.w) + (s2.w + s3.w);
            } else {
                for (int r = 0; r < d.y; r++) {
                    const float4 vv = sp[r * C4];
                    acc.x += vv.x; acc.y += vv.y; acc.z += vv.z; acc.w += vv.w;
                }
            }

            if (d.w) {                         // last chunk of span
                const float inv = __int_as_float(d.z);
                float4 r;
                r.x = acc.x * inv; r.y = acc.y * inv;
                r.z = acc.z * inv; r.w = acc.w * inv;
                reinterpret_cast<float4*>(out)[(size_t)d.x * C4 + tid] = r;
                acc = make_float4(0.f, 0.f, 0.f, 0.f);
            }

            __syncwarp();
            if ((tid & 31) == 0) mbar_arrive(sm32(&mb_empty[c_stg]));
            if (++c_stg == STAGES) { c_stg = 0; c_ph ^= 1; }
        }
    }

    // last block restores steal state for the next (graph) replay
    __syncthreads();
    if (tid == 0) {
        const int dd = atomicAdd(&g_done, 1);
        if (dd == GRID_POOL - 1) {
            g_next = GRID_POOL;
            g_done = 0;
            __threadfence();
        }
    }
}

extern "C" void kernel_launch(void* const* d_in, const int* in_sizes, int n_in,
                              void* d_out, int out_size) {
    const float* emg = (const float*)d_in[0];
    const int*   dur = (const int*)d_in[1];
    float*       out = (float*)d_out;

    pool_tma_kernel<<<GRID_POOL, NTHR>>>(emg, dur, out);
}

// round 15
// speedup vs baseline: 1.1781x; 1.0126x over previous
#include <cuda_runtime.h>
#include <cstdint>

// Shapes fixed by the reference
#define BB 16
#define TT 8192
#define CC 512
#define C4 (CC / 4)              // 128 float4 lanes per frame row
#define YY 256
#define NSPAN (BB * YY)          // 4096
#define ROWB (CC * 4)            // 2048 bytes per frame row
#define RPC 32                   // rows per chunk
#define CHUNKB (RPC * ROWB)      // 65536 bytes per stage
#define STAGES 3
#define NCONS 128                // consumer threads (4 warps)
#define NTHR (NCONS + 32)        // + 1 producer warp
#define BLKS 1                   // 1 block/SM: 192KB ring <= 228KB smem
#define GRID_POOL (148 * BLKS)   // 148

// Steal state (self-restoring each launch; graph-replay safe)
__device__ int g_next = GRID_POOL;
__device__ int g_done = 0;

// ---------------- mbarrier / bulk-copy primitives ----------------
__device__ __forceinline__ uint32_t sm32(const void* p) {
    return (uint32_t)__cvta_generic_to_shared(p);
}
__device__ __forceinline__ void mbar_init(uint32_t a, uint32_t cnt) {
    asm volatile("mbarrier.init.shared.b64 [%0], %1;" :: "r"(a), "r"(cnt) : "memory");
}
__device__ __forceinline__ void mbar_expect_tx(uint32_t a, uint32_t bytes) {
    asm volatile("mbarrier.arrive.expect_tx.shared.b64 _, [%0], %1;"
                 :: "r"(a), "r"(bytes) : "memory");
}
__device__ __forceinline__ void mbar_arrive(uint32_t a) {
    asm volatile("mbarrier.arrive.shared.b64 _, [%0];" :: "r"(a) : "memory");
}
__device__ __forceinline__ void mbar_wait(uint32_t a, uint32_t parity) {
    uint32_t done;
    asm volatile("{\n\t.reg .pred p;\n\t"
                 "mbarrier.try_wait.parity.acquire.cta.shared::cta.b64 p, [%1], %2;\n\t"
                 "selp.b32 %0, 1, 0, p;\n\t}"
                 : "=r"(done) : "r"(a), "r"(parity) : "memory");
    while (!done) {
        asm volatile("{\n\t.reg .pred p;\n\t"
                     "mbarrier.try_wait.parity.acquire.cta.shared::cta.b64 p, [%1], %2, 0x989680;\n\t"
                     "selp.b32 %0, 1, 0, p;\n\t}"
                     : "=r"(done) : "r"(a), "r"(parity) : "memory");
    }
}
__device__ __forceinline__ void bulk_g2s(uint32_t dst, const void* src,
                                         uint32_t bytes, uint32_t mbar) {
    asm volatile("cp.async.bulk.shared::cta.global.mbarrier::complete_tx::bytes "
                 "[%0], [%1], %2, [%3];"
                 :: "r"(dst), "l"(src), "r"(bytes), "r"(mbar) : "memory");
}

// ---------------------------------------------------------------------------
// Warp-specialized persistent kernel (R14 architecture, 64KB chunks,
// 1 block/SM, 3-stage ring with explicit stage/phase cursors).
// Producer warp: steals spans, computes metadata (32-lane reduce over the
// L1-resident durations row), writes zero-spans, streams span data into the
// ring via cp.async.bulk. Terminal descriptor (by=-1) shuts consumers down.
// Consumer warps (128 threads = one float4 lane each): accumulate rows from
// smem per chunk; on a span's last chunk scale by 1/cnt and store.
// Sequential per-span accumulation -> bitwise deterministic.
// ---------------------------------------------------------------------------
__global__ void __launch_bounds__(NTHR, BLKS)
pool_tma_kernel(const float* __restrict__ emg,
                const int*   __restrict__ dur,
                float*       __restrict__ out) {
    __shared__ alignas(128) float4 buf[STAGES][RPC * C4];   // 192 KB ring
    __shared__ alignas(16)  int4   desc[STAGES];            // {by, rows, inv, last}
    __shared__ alignas(8)   unsigned long long mb_full[STAGES];
    __shared__ alignas(8)   unsigned long long mb_empty[STAGES];

    const int tid = threadIdx.x;

    if (tid == 0) {
        #pragma unroll
        for (int s = 0; s < STAGES; s++) {
            mbar_init(sm32(&mb_full[s]),  1);   // producer arrive (expect_tx) + tx
            mbar_init(sm32(&mb_empty[s]), 4);   // one arrive per consumer warp
        }
    }
    __syncthreads();

    if (tid >= NCONS) {
        // ===================== PRODUCER WARP =====================
        const int lane = tid - NCONS;          // 0..31
        const bool leader = (lane == 0);
        const int4* dur4 = reinterpret_cast<const int4*>(dur);
        int p_stg = 0, p_ph = 1;               // producer cursor (phase starts 1)

        int by = blockIdx.x;
        while (by < NSPAN) {
            int nxt = 0;
            if (leader) nxt = atomicAdd(&g_next, 1);   // steal early

            const int b = by >> 8;             // YY == 256
            const int y = by & 255;

            // metadata: 32 lanes x 8 durations each
            const int4 u = __ldg(dur4 + b * 64 + lane * 2);
            const int4 v = __ldg(dur4 + b * 64 + lane * 2 + 1);
            const int base = lane * 8;
            int s = 0;
            if (base + 0 < y) s += u.x;
            if (base + 1 < y) s += u.y;
            if (base + 2 < y) s += u.z;
            if (base + 3 < y) s += u.w;
            if (base + 4 < y) s += v.x;
            if (base + 5 < y) s += v.y;
            if (base + 6 < y) s += v.z;
            if (base + 7 < y) s += v.w;
            int c_lane = 0;
            if ((y >> 3) == lane) {
                switch (y & 7) {
                    case 0:  c_lane = u.x; break;
                    case 1:  c_lane = u.y; break;
                    case 2:  c_lane = u.z; break;
                    case 3:  c_lane = u.w; break;
                    case 4:  c_lane = v.x; break;
                    case 5:  c_lane = v.y; break;
                    case 6:  c_lane = v.z; break;
                    default: c_lane = v.w; break;
                }
            }
            const int start_raw = __reduce_add_sync(0xffffffffu, s);
            const int dcnt = __shfl_sync(0xffffffffu, c_lane, y >> 3);
            const int st  = min(start_raw, TT);
            const int en  = min(start_raw + dcnt, TT);
            const int cnt = en - st;

            if (cnt == 0) {
                // empty span: producer writes the zeros itself
                const float4 z = make_float4(0.f, 0.f, 0.f, 0.f);
                float4* o = reinterpret_cast<float4*>(out) + (size_t)by * C4;
                o[lane]      = z;
                o[lane + 32] = z;
                o[lane + 64] = z;
                o[lane + 96] = z;
            } else if (leader) {
                const char* src = reinterpret_cast<const char*>(emg)
                                  + ((size_t)b * TT + st) * ROWB;
                const float inv = 1.0f / (float)cnt;
                const int nch = (cnt + RPC - 1) >> 5;
                for (int c = 0; c < nch; c++) {
                    const int rows = min(cnt - c * RPC, RPC);
                    mbar_wait(sm32(&mb_empty[p_stg]), p_ph);
                    desc[p_stg] = make_int4(by, rows, __float_as_int(inv),
                                            (c == nch - 1) ? 1 : 0);
                    mbar_expect_tx(sm32(&mb_full[p_stg]), rows * ROWB);
                    bulk_g2s(sm32(&buf[p_stg][0]), src + (size_t)c * CHUNKB,
                             rows * ROWB, sm32(&mb_full[p_stg]));
                    if (++p_stg == STAGES) { p_stg = 0; p_ph ^= 1; }
                }
            }
            by = __shfl_sync(0xffffffffu, nxt, 0);
        }

        // terminal descriptor (dummy 16B copy satisfies the tx count)
        if (leader) {
            mbar_wait(sm32(&mb_empty[p_stg]), p_ph);
            desc[p_stg] = make_int4(-1, 0, 0, 0);
            mbar_expect_tx(sm32(&mb_full[p_stg]), 16);
            bulk_g2s(sm32(&buf[p_stg][0]), emg, 16, sm32(&mb_full[p_stg]));
        }
    } else {
        // ===================== CONSUMER WARPS =====================
        int c_stg = 0, c_ph = 0;               // consumer cursor (phase starts 0)
        float4 acc = make_float4(0.f, 0.f, 0.f, 0.f);
        for (;;) {
            mbar_wait(sm32(&mb_full[c_stg]), c_ph);
            const int4 d = desc[c_stg];        // broadcast LDS
            if (d.x < 0) break;                // terminal

            const float4* sp = &buf[c_stg][tid];
            if (d.y == RPC) {                  // common case: 32 rows
                float4 s0 = make_float4(0.f, 0.f, 0.f, 0.f);
                float4 s1 = s0, s2 = s0, s3 = s0;
                #pragma unroll
                for (int r = 0; r < RPC; r += 4) {
                    const float4 v0 = sp[(r + 0) * C4];
                    const float4 v1 = sp[(r + 1) * C4];
                    const float4 v2 = sp[(r + 2) * C4];
                    const float4 v3 = sp[(r + 3) * C4];
                    s0.x += v0.x; s0.y += v0.y; s0.z += v0.z; s0.w += v0.w;
                    s1.x += v1.x; s1.y += v1.y; s1.z += v1.z; s1.w += v1.w;
                    s2.x += v2.x; s2.y += v2.y; s2.z += v2.z; s2.w += v2.w;
                    s3.x += v3.x; s3.y += v3.y; s3.z += v3.z; s3.w += v3.w;
                }
                acc.x += (s0.x + s1.x) + (s2.x + s3.x);
                acc.y += (s0.y + s1.y) + (s2.y + s3.y);
                acc.z += (s0.z + s1.z) + (s2.z + s3.z);
                acc.w += (s0.w + s1.w) + (s2.w + s3.w);
            } else {
                for (int r = 0; r < d.y; r++) {
                    const float4 vv = sp[r * C4];
                    acc.x += vv.x; acc.y += vv.y; acc.z += vv.z; acc.w += vv.w;
                }
            }

            if (d.w) {                         // last chunk of span
                const float inv = __int_as_float(d.z);
                float4 r;
                r.x = acc.x * inv; r.y = acc.y * inv;
                r.z = acc.z * inv; r.w = acc.w * inv;
                reinterpret_cast<float4*>(out)[(size_t)d.x * C4 + tid] = r;
                acc = make_float4(0.f, 0.f, 0.f, 0.f);
            }

            __syncwarp();
            if ((tid & 31) == 0) mbar_arrive(sm32(&mb_empty[c_stg]));
            if (++c_stg == STAGES) { c_stg = 0; c_ph ^= 1; }
        }
    }

    // last block restores steal state for the next (graph) replay
    __syncthreads();
    if (tid == 0) {
        const int dd = atomicAdd(&g_done, 1);
        if (dd == GRID_POOL - 1) {
            g_next = GRID_POOL;
            g_done = 0;
            __threadfence();
        }
    }
}

extern "C" void kernel_launch(void* const* d_in, const int* in_sizes, int n_in,
                              void* d_out, int out_size) {
    const float* emg = (const float*)d_in[0];
    const int*   dur = (const int*)d_in[1];
    float*       out = (float*)d_out;

    pool_tma_kernel<<<GRID_POOL, NTHR>>>(emg, dur, out);
}